// round 2
// baseline (speedup 1.0000x reference)
#include <cuda_runtime.h>

static constexpr int N_   = 20000;
static constexpr int E_   = 320000;
static constexpr int M_   = 3;
static constexpr int IN_  = 128;
static constexpr int H_   = 4;
static constexpr int D_   = 64;
static constexpr int HD_  = 256;   // H*D
static constexpr int HID_ = 128;

// ---------------- scratch (device globals; no runtime allocation) ----------------
__device__ float g_feat[(size_t)M_ * N_ * HD_];   // 61.4 MB  feat = h @ W[m]
__device__ float g_z   [(size_t)M_ * N_ * HD_];   // 61.4 MB  per-metapath GAT out
__device__ float g_el  [(size_t)M_ * N_ * H_];
__device__ float g_er  [(size_t)M_ * N_ * H_];
__device__ float g_ea  [(size_t)M_ * E_ * H_];    // 15.4 MB  unnormalized alphas (CSR order)
__device__ int   g_deg [M_ * N_];
__device__ int   g_off [M_ * (N_ + 1)];
__device__ int   g_cur [M_ * N_];
__device__ int   g_srcs[M_ * E_];
__device__ int   g_bsum[M_ * 16];
__device__ int   g_boff[M_ * 16];
__device__ float g_wsum[M_];
__device__ float g_beta[M_];

// ---------------- packed fp32x2 FMA (Blackwell; 2x fp32 FMA throughput) ----------
#define UNPACK2(lo, hi, s) asm("mov.b64 {%0, %1}, %2;" : "=r"(lo), "=r"(hi) : "l"(s))
#define FMA2(d, a, b, c)  asm("fma.rn.f32x2 %0, %1, %2, %3;" : "=l"(d) : "l"(a), "l"(b), "l"(c))

__device__ __forceinline__ float lrelu(float x) { return x > 0.f ? x : 0.2f * x; }
__device__ __forceinline__ float fast_tanh(float x) {
    float y; asm("tanh.approx.f32 %0, %1;" : "=f"(y) : "f"(x)); return y;
}

// ---------------- init: zero histogram + wsum ----------------
__global__ void init_kernel() {
    int i = blockIdx.x * blockDim.x + threadIdx.x;
    if (i < M_ * N_) g_deg[i] = 0;
    if (i < M_)      g_wsum[i] = 0.f;
}

// ---------------- GEMM: BM=64, BN=128, BK=16, 256 thr, 4x8/thread, f32x2 ---------
// Packed operands come straight from shared via LDS.64:
//   A stored duplicated as float2 {a,a}; B pairs are naturally adjacent.
// If W2 != nullptr: fused epilogue  wsum[m] += sum tanh(acc+bias)[col]*W2[col]
// (no C store). Else: plain store to C.
__global__ __launch_bounds__(256) void gemm_kernel(
    const float* __restrict__ A, const float* __restrict__ B, float* __restrict__ C,
    int Mrows, int K, int Ncols,
    long aStride, long bStride, long cStride,
    const float* __restrict__ bias, const float* __restrict__ W2)
{
    constexpr int BM = 64, BN = 128, BK = 16;
    __shared__ float2 As2[2][BK][BM];
    __shared__ __align__(16) float Bs[2][BK][BN];
    __shared__ float red[4];

    int bz = blockIdx.z;
    A += (long)bz * aStride; B += (long)bz * bStride; C += (long)bz * cStride;

    int tid = threadIdx.x;
    int tx = tid & 15, ty = tid >> 4;
    int rowBase = blockIdx.x * BM, colBase = blockIdx.y * BN;

    int ar = tid >> 2, ac = (tid & 3) << 2;   // A: 64 rows x 16 k, float4 per thread
    int br = tid >> 4, bc = (tid & 15) << 3;  // B: 16 k x 128 cols, 2x float4 per thread
    bool aValid = (rowBase + ar) < Mrows;

    unsigned long long acc[4][4];
#pragma unroll
    for (int r = 0; r < 4; r++)
#pragma unroll
        for (int j = 0; j < 4; j++) acc[r][j] = 0ull;

    // prologue: tile 0
    float4 a4 = make_float4(0.f, 0.f, 0.f, 0.f);
    if (aValid) a4 = *(const float4*)(A + (long)(rowBase + ar) * K + ac);
    float4 b4a = *(const float4*)(B + (long)br * Ncols + colBase + bc);
    float4 b4b = *(const float4*)(B + (long)br * Ncols + colBase + bc + 4);
    As2[0][ac + 0][ar] = make_float2(a4.x, a4.x);
    As2[0][ac + 1][ar] = make_float2(a4.y, a4.y);
    As2[0][ac + 2][ar] = make_float2(a4.z, a4.z);
    As2[0][ac + 3][ar] = make_float2(a4.w, a4.w);
    *(float4*)&Bs[0][br][bc] = b4a;
    *(float4*)&Bs[0][br][bc + 4] = b4b;
    __syncthreads();

    int buf = 0;
    for (int k0 = BK; k0 < K; k0 += BK) {
        // prefetch next tile to registers
        float4 na = make_float4(0.f, 0.f, 0.f, 0.f);
        if (aValid) na = *(const float4*)(A + (long)(rowBase + ar) * K + k0 + ac);
        float4 nba = *(const float4*)(B + (long)(k0 + br) * Ncols + colBase + bc);
        float4 nbb = *(const float4*)(B + (long)(k0 + br) * Ncols + colBase + bc + 4);

#pragma unroll
        for (int k = 0; k < BK; k++) {
            unsigned long long a2[4], b2[4];
#pragma unroll
            for (int r = 0; r < 4; r++)
                a2[r] = *(const unsigned long long*)&As2[buf][k][(ty << 2) + r];
#pragma unroll
            for (int j = 0; j < 4; j++)
                b2[j] = *(const unsigned long long*)&Bs[buf][k][(tx << 3) + 2 * j];
#pragma unroll
            for (int r = 0; r < 4; r++)
#pragma unroll
                for (int j = 0; j < 4; j++)
                    FMA2(acc[r][j], a2[r], b2[j], acc[r][j]);
        }
        int nb = buf ^ 1;
        As2[nb][ac + 0][ar] = make_float2(na.x, na.x);
        As2[nb][ac + 1][ar] = make_float2(na.y, na.y);
        As2[nb][ac + 2][ar] = make_float2(na.z, na.z);
        As2[nb][ac + 3][ar] = make_float2(na.w, na.w);
        *(float4*)&Bs[nb][br][bc] = nba;
        *(float4*)&Bs[nb][br][bc + 4] = nbb;
        __syncthreads();
        buf = nb;
    }
#pragma unroll
    for (int k = 0; k < BK; k++) {
        unsigned long long a2[4], b2[4];
#pragma unroll
        for (int r = 0; r < 4; r++)
            a2[r] = *(const unsigned long long*)&As2[buf][k][(ty << 2) + r];
#pragma unroll
        for (int j = 0; j < 4; j++)
            b2[j] = *(const unsigned long long*)&Bs[buf][k][(tx << 3) + 2 * j];
#pragma unroll
        for (int r = 0; r < 4; r++)
#pragma unroll
            for (int j = 0; j < 4; j++)
                FMA2(acc[r][j], a2[r], b2[j], acc[r][j]);
    }

    bool fused = (W2 != nullptr);
    if (fused) {
        if (tid < 4) red[tid] = 0.f;
        __syncthreads();
    }

#pragma unroll
    for (int r = 0; r < 4; r++) {
        int row = rowBase + (ty << 2) + r;
        float v[8];
        unsigned int u0, u1;
#pragma unroll
        for (int j = 0; j < 4; j++) {
            UNPACK2(u0, u1, acc[r][j]);
            v[2 * j] = __uint_as_float(u0);
            v[2 * j + 1] = __uint_as_float(u1);
        }
        if (!fused) {
            if (row < Mrows) {
                float* cp = C + (long)row * Ncols + colBase + (tx << 3);
                *(float4*)cp = make_float4(v[0], v[1], v[2], v[3]);
                *(float4*)(cp + 4) = make_float4(v[4], v[5], v[6], v[7]);
            }
        } else {
            if (row < Mrows) {
                int m = row / N_;
                float s = 0.f;
#pragma unroll
                for (int j = 0; j < 8; j++) {
                    int col = colBase + (tx << 3) + j;
                    float t = fast_tanh(v[j] + bias[col]);
                    s += t * W2[col];
                }
                atomicAdd(&red[m], s);
            }
        }
    }
    if (fused) {
        __syncthreads();
        if (tid < 3) atomicAdd(&g_wsum[tid], red[tid]);
    }
}

// ---------------- el/er: per-node attention logit halves ----------------
__global__ void elr_kernel(const float* __restrict__ attn_l,
                           const float* __restrict__ attn_r) {
    int g = blockIdx.x * blockDim.x + threadIdx.x;
    int warp = g >> 5, lane = g & 31;
    if (warp >= M_ * N_) return;
    int m = warp / N_;
    const float* frow = g_feat + (size_t)warp * HD_;
    const float* al = attn_l + m * HD_;
    const float* ar = attn_r + m * HD_;
    float el[4] = {0, 0, 0, 0}, er[4] = {0, 0, 0, 0};
#pragma unroll
    for (int k = 0; k < 8; k++) {
        int c = lane + (k << 5);
        float f = frow[c];
        el[k >> 1] += f * al[c];
        er[k >> 1] += f * ar[c];
    }
#pragma unroll
    for (int h = 0; h < 4; h++) {
#pragma unroll
        for (int s = 16; s > 0; s >>= 1) {
            el[h] += __shfl_xor_sync(0xffffffffu, el[h], s);
            er[h] += __shfl_xor_sync(0xffffffffu, er[h], s);
        }
    }
    if (lane == 0) {
        *(float4*)&g_el[(size_t)warp * 4] = make_float4(el[0], el[1], el[2], el[3]);
        *(float4*)&g_er[(size_t)warp * 4] = make_float4(er[0], er[1], er[2], er[3]);
    }
}

// ---------------- CSR build: histogram -> 3-stage scan -> scatter ----------------
__global__ void hist_kernel(const int* __restrict__ dst) {
    int i = blockIdx.x * blockDim.x + threadIdx.x;
    if (i >= M_ * E_) return;
    int m = i / E_;
    atomicAdd(&g_deg[m * N_ + dst[i]], 1);
}

__global__ void scan1_kernel() {   // grid (10, M_), 256 thr, 2048 nodes/block
    int m = blockIdx.y, b = blockIdx.x, t = threadIdx.x;
    int i0 = b * 2048 + t * 8;
    int v[8];
    int s = 0;
#pragma unroll
    for (int j = 0; j < 8; j++) {
        int i = i0 + j;
        int d = (i < N_) ? g_deg[m * N_ + i] : 0;
        s += d; v[j] = s;
    }
    __shared__ int sh[256];
    sh[t] = s;
    __syncthreads();
#pragma unroll
    for (int st = 1; st < 256; st <<= 1) {
        int y = (t >= st) ? sh[t - st] : 0;
        __syncthreads();
        sh[t] += y;
        __syncthreads();
    }
    int excl = sh[t] - s;
#pragma unroll
    for (int j = 0; j < 8; j++) {
        int i = i0 + j;
        if (i < N_) g_off[m * (N_ + 1) + i + 1] = excl + v[j];
    }
    if (t == 255) g_bsum[m * 16 + b] = sh[255];
}

__global__ void scan2_kernel() {   // 1 block, M_ threads
    int m = threadIdx.x;
    if (m < M_) {
        int run = 0;
        for (int b = 0; b < 10; b++) { g_boff[m * 16 + b] = run; run += g_bsum[m * 16 + b]; }
    }
}

__global__ void scan3_kernel() {
    int i = blockIdx.x * blockDim.x + threadIdx.x;
    if (i >= M_ * N_) return;
    int m = i / N_, n = i - m * N_;
    int off1 = g_off[m * (N_ + 1) + n + 1] + g_boff[m * 16 + (n >> 11)];
    g_off[m * (N_ + 1) + n + 1] = off1;
    g_cur[i] = off1 - g_deg[i];
    if (n == 0) g_off[m * (N_ + 1)] = 0;
}

__global__ void scatter_kernel(const int* __restrict__ src,
                               const int* __restrict__ dst) {
    int i = blockIdx.x * blockDim.x + threadIdx.x;
    if (i >= M_ * E_) return;
    int m = i / E_;
    int d = dst[i];
    int pos = atomicAdd(&g_cur[m * N_ + d], 1);
    g_srcs[m * E_ + pos] = src[i];
}

// ---------------- GAT aggregate: one warp per (metapath, dst node) ----------------
// pass A: per-lane over edges -> unnormalized alpha (stored) + per-head sums
// pass B: serial over edges, warp-wide coalesced feature gather, weighted sum
__global__ __launch_bounds__(256) void agg_kernel(const float* __restrict__ bias) {
    int g = blockIdx.x * blockDim.x + threadIdx.x;
    int warp = g >> 5, lane = g & 31;
    if (warp >= M_ * N_) return;
    int m = warp / N_;
    int n = warp - m * N_;
    int start = g_off[m * (N_ + 1) + n];
    int end   = g_off[m * (N_ + 1) + n + 1];

    float4 erd = *(const float4*)&g_er[(size_t)warp * 4];
    const int*   sl  = g_srcs + m * E_;
    const float* elb = g_el  + (size_t)m * N_ * 4;
    float*       eab = g_ea  + (size_t)m * E_ * 4;
    const float* fb  = g_feat + (size_t)m * N_ * HD_;

    // pass A: alphas + sums (1 exp per (edge,head), lane-parallel)
    float s0 = 0, s1 = 0, s2 = 0, s3 = 0;
    for (int i = start + lane; i < end; i += 32) {
        float4 e4 = *(const float4*)&elb[(size_t)sl[i] * 4];
        float p0 = __expf(lrelu(e4.x + erd.x));
        float p1 = __expf(lrelu(e4.y + erd.y));
        float p2 = __expf(lrelu(e4.z + erd.z));
        float p3 = __expf(lrelu(e4.w + erd.w));
        s0 += p0; s1 += p1; s2 += p2; s3 += p3;
        *(float4*)&eab[(size_t)i * 4] = make_float4(p0, p1, p2, p3);
    }
#pragma unroll
    for (int s = 16; s > 0; s >>= 1) {
        s0 += __shfl_xor_sync(0xffffffffu, s0, s);
        s1 += __shfl_xor_sync(0xffffffffu, s1, s);
        s2 += __shfl_xor_sync(0xffffffffu, s2, s);
        s3 += __shfl_xor_sync(0xffffffffu, s3, s);
    }
    float r0 = 1.f / fmaxf(s0, 1e-9f);
    float r1 = 1.f / fmaxf(s1, 1e-9f);
    float r2 = 1.f / fmaxf(s2, 1e-9f);
    float r3 = 1.f / fmaxf(s3, 1e-9f);

    // lane covers cols [lane*4, lane*4+4) (head lane/16) and [128+lane*4, ..) (head 2+lane/16)
    int hi = lane >> 4;
    float rA = hi ? r1 : r0;
    float rB = hi ? r3 : r2;
    int colA = lane << 2;

    float4 accA = make_float4(0.f, 0.f, 0.f, 0.f);
    float4 accB = make_float4(0.f, 0.f, 0.f, 0.f);
    int i = start;
    for (; i + 2 <= end; i += 2) {
        float4 ea0 = *(const float4*)&eab[(size_t)i * 4];
        float4 ea1 = *(const float4*)&eab[(size_t)(i + 1) * 4];
        int sA = sl[i], sB = sl[i + 1];
        const float* f0 = fb + (size_t)sA * HD_;
        const float* f1 = fb + (size_t)sB * HD_;
        float4 f0a = *(const float4*)(f0 + colA);
        float4 f0b = *(const float4*)(f0 + 128 + colA);
        float4 f1a = *(const float4*)(f1 + colA);
        float4 f1b = *(const float4*)(f1 + 128 + colA);
        float a0A = (hi ? ea0.y : ea0.x) * rA;
        float a0B = (hi ? ea0.w : ea0.z) * rB;
        float a1A = (hi ? ea1.y : ea1.x) * rA;
        float a1B = (hi ? ea1.w : ea1.z) * rB;
        accA.x += a0A * f0a.x + a1A * f1a.x;
        accA.y += a0A * f0a.y + a1A * f1a.y;
        accA.z += a0A * f0a.z + a1A * f1a.z;
        accA.w += a0A * f0a.w + a1A * f1a.w;
        accB.x += a0B * f0b.x + a1B * f1b.x;
        accB.y += a0B * f0b.y + a1B * f1b.y;
        accB.z += a0B * f0b.z + a1B * f1b.z;
        accB.w += a0B * f0b.w + a1B * f1b.w;
    }
    if (i < end) {
        float4 ea0 = *(const float4*)&eab[(size_t)i * 4];
        int sA = sl[i];
        const float* f0 = fb + (size_t)sA * HD_;
        float4 f0a = *(const float4*)(f0 + colA);
        float4 f0b = *(const float4*)(f0 + 128 + colA);
        float a0A = (hi ? ea0.y : ea0.x) * rA;
        float a0B = (hi ? ea0.w : ea0.z) * rB;
        accA.x += a0A * f0a.x; accA.y += a0A * f0a.y;
        accA.z += a0A * f0a.z; accA.w += a0A * f0a.w;
        accB.x += a0B * f0b.x; accB.y += a0B * f0b.y;
        accB.z += a0B * f0b.z; accB.w += a0B * f0b.w;
    }

    float4 bA = *(const float4*)(bias + m * HD_ + colA);
    float4 bB = *(const float4*)(bias + m * HD_ + 128 + colA);
    accA.x += bA.x; accA.y += bA.y; accA.z += bA.z; accA.w += bA.w;
    accB.x += bB.x; accB.y += bB.y; accB.z += bB.z; accB.w += bB.w;
    float* zr = g_z + (size_t)warp * HD_;
    *(float4*)(zr + colA) = accA;
    *(float4*)(zr + 128 + colA) = accB;
}

// ---------------- beta + final mix ----------------
__global__ void beta_kernel() {
    if (threadIdx.x == 0 && blockIdx.x == 0) {
        float w0 = g_wsum[0] / (float)N_;
        float w1 = g_wsum[1] / (float)N_;
        float w2 = g_wsum[2] / (float)N_;
        float mx = fmaxf(w0, fmaxf(w1, w2));
        float e0 = expf(w0 - mx), e1 = expf(w1 - mx), e2 = expf(w2 - mx);
        float s = e0 + e1 + e2;
        g_beta[0] = e0 / s; g_beta[1] = e1 / s; g_beta[2] = e2 / s;
    }
}

__global__ void final_kernel(float* __restrict__ out) {
    int i = blockIdx.x * blockDim.x + threadIdx.x;
    constexpr int S = N_ * HD_ / 4;
    if (i >= S) return;
    float b0 = g_beta[0], b1 = g_beta[1], b2 = g_beta[2];
    const float4* z = (const float4*)g_z;
    float4 v0 = z[i], v1 = z[i + S], v2 = z[i + 2 * S];
    float4 r;
    r.x = b0 * v0.x + b1 * v1.x + b2 * v2.x;
    r.y = b0 * v0.y + b1 * v1.y + b2 * v2.y;
    r.z = b0 * v0.z + b1 * v1.z + b2 * v2.z;
    r.w = b0 * v0.w + b1 * v1.w + b2 * v2.w;
    ((float4*)out)[i] = r;
}

// ---------------- launch ----------------
extern "C" void kernel_launch(void* const* d_in, const int* in_sizes, int n_in,
                              void* d_out, int out_size) {
    const float* h      = (const float*)d_in[0];
    const int*   src    = (const int*)d_in[1];
    const int*   dst    = (const int*)d_in[2];
    const float* W      = (const float*)d_in[3];
    const float* attn_l = (const float*)d_in[4];
    const float* attn_r = (const float*)d_in[5];
    const float* bias   = (const float*)d_in[6];
    const float* sem_W1 = (const float*)d_in[7];
    const float* sem_b1 = (const float*)d_in[8];
    const float* sem_W2 = (const float*)d_in[9];
    float* out = (float*)d_out;

    float *feat, *z;
    cudaGetSymbolAddress((void**)&feat, g_feat);
    cudaGetSymbolAddress((void**)&z, g_z);

    init_kernel<<<(M_ * N_ + 255) / 256, 256>>>();

    // GEMM1: feat[m] = h @ W[m]
    gemm_kernel<<<dim3((N_ + 63) / 64, HD_ / 128, M_), 256>>>(
        h, W, feat, N_, IN_, HD_,
        0L, (long)IN_ * HD_, (long)N_ * HD_, nullptr, nullptr);

    elr_kernel<<<(M_ * N_ * 32 + 255) / 256, 256>>>(attn_l, attn_r);

    hist_kernel<<<(M_ * E_ + 255) / 256, 256>>>(dst);
    scan1_kernel<<<dim3(10, M_), 256>>>();
    scan2_kernel<<<1, 32>>>();
    scan3_kernel<<<(M_ * N_ + 255) / 256, 256>>>();
    scatter_kernel<<<(M_ * E_ + 255) / 256, 256>>>(src, dst);

    agg_kernel<<<(M_ * N_ * 32 + 255) / 256, 256>>>(bias);

    // GEMM2 fused: wsum[m] += sum_n tanh(z@W1+b1) . W2   (no output store)
    gemm_kernel<<<dim3((M_ * N_ + 63) / 64, 1, 1), 256>>>(
        z, sem_W1, feat /*unused*/, M_ * N_, HD_, HID_,
        0L, 0L, 0L, sem_b1, sem_W2);

    beta_kernel<<<1, 32>>>();
    final_kernel<<<(N_ * HD_ / 4 + 255) / 256, 256>>>(out);
}

// round 3
// speedup vs baseline: 1.3990x; 1.3990x over previous
#include <cuda_runtime.h>

static constexpr int N_   = 20000;
static constexpr int E_   = 320000;
static constexpr int M_   = 3;
static constexpr int IN_  = 128;
static constexpr int H_   = 4;
static constexpr int D_   = 64;
static constexpr int HD_  = 256;   // H*D
static constexpr int HID_ = 128;

// ---------------- scratch (device globals; no runtime allocation) ----------------
__device__ float g_feat[(size_t)M_ * N_ * HD_];   // 61.4 MB
__device__ float g_z   [(size_t)M_ * N_ * HD_];   // 61.4 MB
__device__ float g_el  [(size_t)M_ * N_ * H_];
__device__ float g_er  [(size_t)M_ * N_ * H_];
__device__ float g_ea  [(size_t)M_ * E_ * H_];    // 15.4 MB unnormalized alphas (CSR order)
__device__ int   g_deg [M_ * N_];
__device__ int   g_off [M_ * (N_ + 1)];
__device__ int   g_cur [M_ * N_];
__device__ int   g_srcs[M_ * E_];
__device__ int   g_bsum[M_ * 16];
__device__ int   g_boff[M_ * 16];
__device__ float g_wsum[M_];
__device__ float g_beta[M_];

// ---------------- packed fp32x2 FMA ----------------
#define PACK2(d, lo, hi)  asm("mov.b64 %0, {%1, %2};" : "=l"(d) : "r"(lo), "r"(hi))
#define UNPACK2(lo, hi, s) asm("mov.b64 {%0, %1}, %2;" : "=r"(lo), "=r"(hi) : "l"(s))
#define FMA2(d, a, b, c)  asm("fma.rn.f32x2 %0, %1, %2, %3;" : "=l"(d) : "l"(a), "l"(b), "l"(c))

__device__ __forceinline__ float lrelu(float x) { return x > 0.f ? x : 0.2f * x; }
__device__ __forceinline__ float fast_tanh(float x) {
    float y; asm("tanh.approx.f32 %0, %1;" : "=f"(y) : "f"(x)); return y;
}

// ---------------- init ----------------
__global__ void init_kernel() {
    int i = blockIdx.x * blockDim.x + threadIdx.x;
    if (i < M_ * N_) g_deg[i] = 0;
    if (i < M_)      g_wsum[i] = 0.f;
}

// ---------------- tiled GEMM (round-1 proven layout: BM=64,BN=64,BK=16) ----------
// If W2 != nullptr: fused epilogue wsum[m] += sum_col tanh(acc+bias)*W2 (no store).
__global__ __launch_bounds__(256) void gemm_kernel(
    const float* __restrict__ A, const float* __restrict__ B, float* __restrict__ C,
    int Mrows, int K, int Ncols,
    long aStride, long bStride, long cStride,
    const float* __restrict__ bias, const float* __restrict__ W2)
{
    constexpr int BM = 64, BN = 64, BK = 16;
    __shared__ float As[BK][BM + 4];
    __shared__ float Bs[BK][BN];
    __shared__ float red[4];
    int bz = blockIdx.z;
    A += (long)bz * aStride; B += (long)bz * bStride; C += (long)bz * cStride;

    int tid = threadIdx.x;
    int tx = tid & 15, ty = tid >> 4;
    int rowBase = blockIdx.x * BM, colBase = blockIdx.y * BN;

    unsigned long long acc[4][2];
#pragma unroll
    for (int i = 0; i < 4; i++) { acc[i][0] = 0ull; acc[i][1] = 0ull; }

    int ar = tid >> 2,  ac = (tid & 3)  << 2;
    int br = tid >> 4,  bc = (tid & 15) << 2;

    for (int k0 = 0; k0 < K; k0 += BK) {
        float4 a4 = make_float4(0.f, 0.f, 0.f, 0.f);
        if (rowBase + ar < Mrows)
            a4 = *(const float4*)(A + (long)(rowBase + ar) * K + (k0 + ac));
        As[ac + 0][ar] = a4.x; As[ac + 1][ar] = a4.y;
        As[ac + 2][ar] = a4.z; As[ac + 3][ar] = a4.w;
        float4 b4 = *(const float4*)(B + (long)(k0 + br) * Ncols + (colBase + bc));
        *(float4*)&Bs[br][bc] = b4;
        __syncthreads();
#pragma unroll
        for (int k = 0; k < BK; k++) {
            float4 ra = *(const float4*)&As[k][ty << 2];
            float4 rb = *(const float4*)&Bs[k][tx << 2];
            unsigned long long b01, b23;
            PACK2(b01, __float_as_uint(rb.x), __float_as_uint(rb.y));
            PACK2(b23, __float_as_uint(rb.z), __float_as_uint(rb.w));
            float rav[4] = {ra.x, ra.y, ra.z, ra.w};
#pragma unroll
            for (int i = 0; i < 4; i++) {
                unsigned long long a2;
                unsigned int au = __float_as_uint(rav[i]);
                PACK2(a2, au, au);
                FMA2(acc[i][0], a2, b01, acc[i][0]);
                FMA2(acc[i][1], a2, b23, acc[i][1]);
            }
        }
        __syncthreads();
    }

    bool fused = (W2 != nullptr);
    if (fused) {
        if (tid < 4) red[tid] = 0.f;
        __syncthreads();
    }

#pragma unroll
    for (int i = 0; i < 4; i++) {
        int row = rowBase + (ty << 2) + i;
        if (row >= Mrows) continue;
        int col = colBase + (tx << 2);
        float v[4];
        unsigned int u0, u1;
        UNPACK2(u0, u1, acc[i][0]); v[0] = __uint_as_float(u0); v[1] = __uint_as_float(u1);
        UNPACK2(u0, u1, acc[i][1]); v[2] = __uint_as_float(u0); v[3] = __uint_as_float(u1);
        if (!fused) {
            *(float4*)(C + (long)row * Ncols + col) = make_float4(v[0], v[1], v[2], v[3]);
        } else {
            int m = row / N_;
            float s = 0.f;
#pragma unroll
            for (int j = 0; j < 4; j++)
                s += fast_tanh(v[j] + bias[col + j]) * W2[col + j];
            atomicAdd(&red[m], s);
        }
    }
    if (fused) {
        __syncthreads();
        if (tid < 3) atomicAdd(&g_wsum[tid], red[tid]);
    }
}

// ---------------- el/er ----------------
__global__ void elr_kernel(const float* __restrict__ attn_l,
                           const float* __restrict__ attn_r) {
    int g = blockIdx.x * blockDim.x + threadIdx.x;
    int warp = g >> 5, lane = g & 31;
    if (warp >= M_ * N_) return;
    int m = warp / N_;
    const float* frow = g_feat + (size_t)warp * HD_;
    const float* al = attn_l + m * HD_;
    const float* ar = attn_r + m * HD_;
    float el[4] = {0, 0, 0, 0}, er[4] = {0, 0, 0, 0};
#pragma unroll
    for (int k = 0; k < 8; k++) {
        int c = lane + (k << 5);
        float f = frow[c];
        el[k >> 1] += f * al[c];
        er[k >> 1] += f * ar[c];
    }
#pragma unroll
    for (int h = 0; h < 4; h++) {
#pragma unroll
        for (int s = 16; s > 0; s >>= 1) {
            el[h] += __shfl_xor_sync(0xffffffffu, el[h], s);
            er[h] += __shfl_xor_sync(0xffffffffu, er[h], s);
        }
    }
    if (lane == 0) {
        *(float4*)&g_el[(size_t)warp * 4] = make_float4(el[0], el[1], el[2], el[3]);
        *(float4*)&g_er[(size_t)warp * 4] = make_float4(er[0], er[1], er[2], er[3]);
    }
}

// ---------------- CSR build ----------------
__global__ void hist_kernel(const int* __restrict__ dst) {
    int i = blockIdx.x * blockDim.x + threadIdx.x;
    if (i >= M_ * E_) return;
    int m = i / E_;
    atomicAdd(&g_deg[m * N_ + dst[i]], 1);
}

__global__ void scan1_kernel() {   // grid (10, M_), 2048 nodes/block
    int m = blockIdx.y, b = blockIdx.x, t = threadIdx.x;
    int i0 = b * 2048 + t * 8;
    int v[8];
    int s = 0;
#pragma unroll
    for (int j = 0; j < 8; j++) {
        int i = i0 + j;
        int d = (i < N_) ? g_deg[m * N_ + i] : 0;
        s += d; v[j] = s;
    }
    __shared__ int sh[256];
    sh[t] = s;
    __syncthreads();
#pragma unroll
    for (int st = 1; st < 256; st <<= 1) {
        int y = (t >= st) ? sh[t - st] : 0;
        __syncthreads();
        sh[t] += y;
        __syncthreads();
    }
    int excl = sh[t] - s;
#pragma unroll
    for (int j = 0; j < 8; j++) {
        int i = i0 + j;
        if (i < N_) g_off[m * (N_ + 1) + i + 1] = excl + v[j];
    }
    if (t == 255) g_bsum[m * 16 + b] = sh[255];
}

__global__ void scan2_kernel() {
    int m = threadIdx.x;
    if (m < M_) {
        int run = 0;
        for (int b = 0; b < 10; b++) { g_boff[m * 16 + b] = run; run += g_bsum[m * 16 + b]; }
    }
}

__global__ void scan3_kernel() {
    int i = blockIdx.x * blockDim.x + threadIdx.x;
    if (i >= M_ * N_) return;
    int m = i / N_, n = i - m * N_;
    int off1 = g_off[m * (N_ + 1) + n + 1] + g_boff[m * 16 + (n >> 11)];
    g_off[m * (N_ + 1) + n + 1] = off1;
    g_cur[i] = off1 - g_deg[i];
    if (n == 0) g_off[m * (N_ + 1)] = 0;
}

__global__ void scatter_kernel(const int* __restrict__ src,
                               const int* __restrict__ dst) {
    int i = blockIdx.x * blockDim.x + threadIdx.x;
    if (i >= M_ * E_) return;
    int m = i / E_;
    int d = dst[i];
    int pos = atomicAdd(&g_cur[m * N_ + d], 1);
    g_srcs[m * E_ + pos] = src[i];
}

// ---------------- GAT aggregate: one warp per (metapath, dst) -------------------
// pass A: exp once per (edge,head), store to g_ea (contiguous), reduce sums
// pass B: serial edges, coalesced float4 feature gather, multiply cached alpha
__global__ __launch_bounds__(256) void agg_kernel(const float* __restrict__ bias) {
    int g = blockIdx.x * blockDim.x + threadIdx.x;
    int warp = g >> 5, lane = g & 31;
    if (warp >= M_ * N_) return;
    int m = warp / N_;
    int n = warp - m * N_;
    int start = g_off[m * (N_ + 1) + n];
    int end   = g_off[m * (N_ + 1) + n + 1];

    float4 erd = *(const float4*)&g_er[(size_t)warp * 4];
    const int*   sl  = g_srcs + m * E_;
    const float* elb = g_el  + (size_t)m * N_ * 4;
    float*       eab = g_ea  + (size_t)m * E_ * 4;
    const float* fb  = g_feat + (size_t)m * N_ * HD_;

    float s0 = 0, s1 = 0, s2 = 0, s3 = 0;
    for (int i = start + lane; i < end; i += 32) {
        float4 e4 = *(const float4*)&elb[(size_t)sl[i] * 4];
        float p0 = __expf(lrelu(e4.x + erd.x));
        float p1 = __expf(lrelu(e4.y + erd.y));
        float p2 = __expf(lrelu(e4.z + erd.z));
        float p3 = __expf(lrelu(e4.w + erd.w));
        s0 += p0; s1 += p1; s2 += p2; s3 += p3;
        *(float4*)&eab[(size_t)i * 4] = make_float4(p0, p1, p2, p3);
    }
#pragma unroll
    for (int s = 16; s > 0; s >>= 1) {
        s0 += __shfl_xor_sync(0xffffffffu, s0, s);
        s1 += __shfl_xor_sync(0xffffffffu, s1, s);
        s2 += __shfl_xor_sync(0xffffffffu, s2, s);
        s3 += __shfl_xor_sync(0xffffffffu, s3, s);
    }
    float r0 = 1.f / fmaxf(s0, 1e-9f);
    float r1 = 1.f / fmaxf(s1, 1e-9f);
    float r2 = 1.f / fmaxf(s2, 1e-9f);
    float r3 = 1.f / fmaxf(s3, 1e-9f);

    int hi = lane >> 4;
    float rA = hi ? r1 : r0;
    float rB = hi ? r3 : r2;
    int colA = lane << 2;

    float4 accA = make_float4(0.f, 0.f, 0.f, 0.f);
    float4 accB = make_float4(0.f, 0.f, 0.f, 0.f);
    int i = start;
    for (; i + 2 <= end; i += 2) {
        float4 ea0 = *(const float4*)&eab[(size_t)i * 4];
        float4 ea1 = *(const float4*)&eab[(size_t)(i + 1) * 4];
        int sA = sl[i], sB = sl[i + 1];
        const float* f0 = fb + (size_t)sA * HD_;
        const float* f1 = fb + (size_t)sB * HD_;
        float4 f0a = *(const float4*)(f0 + colA);
        float4 f0b = *(const float4*)(f0 + 128 + colA);
        float4 f1a = *(const float4*)(f1 + colA);
        float4 f1b = *(const float4*)(f1 + 128 + colA);
        float a0A = (hi ? ea0.y : ea0.x) * rA;
        float a0B = (hi ? ea0.w : ea0.z) * rB;
        float a1A = (hi ? ea1.y : ea1.x) * rA;
        float a1B = (hi ? ea1.w : ea1.z) * rB;
        accA.x += a0A * f0a.x + a1A * f1a.x;
        accA.y += a0A * f0a.y + a1A * f1a.y;
        accA.z += a0A * f0a.z + a1A * f1a.z;
        accA.w += a0A * f0a.w + a1A * f1a.w;
        accB.x += a0B * f0b.x + a1B * f1b.x;
        accB.y += a0B * f0b.y + a1B * f1b.y;
        accB.z += a0B * f0b.z + a1B * f1b.z;
        accB.w += a0B * f0b.w + a1B * f1b.w;
    }
    if (i < end) {
        float4 ea0 = *(const float4*)&eab[(size_t)i * 4];
        int sA = sl[i];
        const float* f0 = fb + (size_t)sA * HD_;
        float4 f0a = *(const float4*)(f0 + colA);
        float4 f0b = *(const float4*)(f0 + 128 + colA);
        float a0A = (hi ? ea0.y : ea0.x) * rA;
        float a0B = (hi ? ea0.w : ea0.z) * rB;
        accA.x += a0A * f0a.x; accA.y += a0A * f0a.y;
        accA.z += a0A * f0a.z; accA.w += a0A * f0a.w;
        accB.x += a0B * f0b.x; accB.y += a0B * f0b.y;
        accB.z += a0B * f0b.z; accB.w += a0B * f0b.w;
    }

    float4 bA = *(const float4*)(bias + m * HD_ + colA);
    float4 bB = *(const float4*)(bias + m * HD_ + 128 + colA);
    accA.x += bA.x; accA.y += bA.y; accA.z += bA.z; accA.w += bA.w;
    accB.x += bB.x; accB.y += bB.y; accB.z += bB.z; accB.w += bB.w;
    float* zr = g_z + (size_t)warp * HD_;
    *(float4*)(zr + colA) = accA;
    *(float4*)(zr + 128 + colA) = accB;
}

// ---------------- beta + final mix ----------------
__global__ void beta_kernel() {
    if (threadIdx.x == 0 && blockIdx.x == 0) {
        float w0 = g_wsum[0] / (float)N_;
        float w1 = g_wsum[1] / (float)N_;
        float w2 = g_wsum[2] / (float)N_;
        float mx = fmaxf(w0, fmaxf(w1, w2));
        float e0 = expf(w0 - mx), e1 = expf(w1 - mx), e2 = expf(w2 - mx);
        float s = e0 + e1 + e2;
        g_beta[0] = e0 / s; g_beta[1] = e1 / s; g_beta[2] = e2 / s;
    }
}

__global__ void final_kernel(float* __restrict__ out) {
    int i = blockIdx.x * blockDim.x + threadIdx.x;
    constexpr int S = N_ * HD_ / 4;
    if (i >= S) return;
    float b0 = g_beta[0], b1 = g_beta[1], b2 = g_beta[2];
    const float4* z = (const float4*)g_z;
    float4 v0 = z[i], v1 = z[i + S], v2 = z[i + 2 * S];
    float4 r;
    r.x = b0 * v0.x + b1 * v1.x + b2 * v2.x;
    r.y = b0 * v0.y + b1 * v1.y + b2 * v2.y;
    r.z = b0 * v0.z + b1 * v1.z + b2 * v2.z;
    r.w = b0 * v0.w + b1 * v1.w + b2 * v2.w;
    ((float4*)out)[i] = r;
}

// ---------------- launch ----------------
extern "C" void kernel_launch(void* const* d_in, const int* in_sizes, int n_in,
                              void* d_out, int out_size) {
    const float* h      = (const float*)d_in[0];
    const int*   src    = (const int*)d_in[1];
    const int*   dst    = (const int*)d_in[2];
    const float* W      = (const float*)d_in[3];
    const float* attn_l = (const float*)d_in[4];
    const float* attn_r = (const float*)d_in[5];
    const float* bias   = (const float*)d_in[6];
    const float* sem_W1 = (const float*)d_in[7];
    const float* sem_b1 = (const float*)d_in[8];
    const float* sem_W2 = (const float*)d_in[9];
    float* out = (float*)d_out;

    float *feat, *z;
    cudaGetSymbolAddress((void**)&feat, g_feat);
    cudaGetSymbolAddress((void**)&z, g_z);

    init_kernel<<<(M_ * N_ + 255) / 256, 256>>>();

    // GEMM1: feat[m] = h @ W[m]
    gemm_kernel<<<dim3((N_ + 63) / 64, HD_ / 64, M_), 256>>>(
        h, W, feat, N_, IN_, HD_,
        0L, (long)IN_ * HD_, (long)N_ * HD_, nullptr, nullptr);

    elr_kernel<<<(M_ * N_ * 32 + 255) / 256, 256>>>(attn_l, attn_r);

    hist_kernel<<<(M_ * E_ + 255) / 256, 256>>>(dst);
    scan1_kernel<<<dim3(10, M_), 256>>>();
    scan2_kernel<<<1, 32>>>();
    scan3_kernel<<<(M_ * N_ + 255) / 256, 256>>>();
    scatter_kernel<<<(M_ * E_ + 255) / 256, 256>>>(src, dst);

    agg_kernel<<<(M_ * N_ * 32 + 255) / 256, 256>>>(bias);

    // GEMM2 fused: wsum[m] += sum tanh(z@W1+b1) . W2   (no output store)
    gemm_kernel<<<dim3((M_ * N_ + 63) / 64, HID_ / 64, 1), 256>>>(
        z, sem_W1, feat /*unused*/, M_ * N_, HD_, HID_,
        0L, 0L, 0L, sem_b1, sem_W2);

    beta_kernel<<<1, 32>>>();
    final_kernel<<<(N_ * HD_ / 4 + 255) / 256, 256>>>(out);
}